// round 11
// baseline (speedup 1.0000x reference)
#include <cuda_runtime.h>

#define NCLS   8192
#define NBATCH 8192
#define THREADS 256
#define NWARPS (THREADS / 32)
#define NITER  ((NCLS / 4) / THREADS)   // 8 float4-iterations per thread
#define STAGES 4
#define EPSF 1e-8f
#define DEPTH_PARAM 0.1f
#define FULLMASK 0xffffffffu

// Global accumulator + completion counter. Zero-initialized at module load;
// the last-finishing row resets both before the kernel ends, so every
// kernel_launch call starts from identical state.
__device__ double       g_acc;
__device__ unsigned int g_done;

__device__ __forceinline__ void cp_async16(void* smem_dst, const void* gmem_src) {
    unsigned int s = (unsigned int)__cvta_generic_to_shared(smem_dst);
    asm volatile("cp.async.cg.shared.global [%0], [%1], 16;"
                 :: "r"(s), "l"(gmem_src) : "memory");
}
#define CP_COMMIT() asm volatile("cp.async.commit_group;" ::: "memory")
#define CP_WAIT3()  asm volatile("cp.async.wait_group 3;"  ::: "memory")

__global__ __launch_bounds__(THREADS)
void chce_fused_kernel(const float* __restrict__ y_pred,
                       const float* __restrict__ y_true,
                       const float* __restrict__ class_w,
                       const int*   __restrict__ tree_paths,
                       const int*   __restrict__ tree_lens,
                       float*       __restrict__ out,
                       int D)
{
    const int b    = blockIdx.x;
    const int tid  = threadIdx.x;
    const int lane = tid & 31;
    const int warp = tid >> 5;

    // Per-warp private staging ring for y_true: each lane copies and reads
    // ONLY its own 16B slot -> no cross-warp or cross-lane sync needed;
    // cp.async per-thread wait_group provides the ordering.
    __shared__ float4 sh_t[NWARPS][STAGES][32];
    __shared__ float  sh_v[NWARPS];
    __shared__ int    sh_i[NWARPS];
    __shared__ float  sh_s[NWARPS];

    const float4* yp = reinterpret_cast<const float4*>(y_pred) + (size_t)b * (NCLS / 4);
    const float4* yt = reinterpret_cast<const float4*>(y_true) + (size_t)b * (NCLS / 4);

    // Prologue: fill all STAGES slots (deep in-flight y_true stream).
    #pragma unroll
    for (int s = 0; s < STAGES; ++s) {
        cp_async16(&sh_t[warp][s][lane], &yt[tid + s * THREADS]);
        CP_COMMIT();
    }

    float sumexp = 0.0f;
    float best_v = -3.402823466e38f;
    int   best_i = 0;

    #pragma unroll
    for (int it = 0; it < NITER; ++it) {
        const int idx = tid + it * THREADS;
        float4 p = __ldcs(&yp[idx]);           // register-path stream

        CP_WAIT3();                            // stage `it` complete
        float4 t = sh_t[warp][it & (STAGES - 1)][lane];

        // Refill ring for iter it+STAGES (empty commit keeps wait depth uniform).
        if (it + STAGES < NITER)
            cp_async16(&sh_t[warp][(it + STAGES) & (STAGES - 1)][lane],
                       &yt[tid + (it + STAGES) * THREADS]);
        CP_COMMIT();

        sumexp += __expf(p.x) + __expf(p.y) + __expf(p.z) + __expf(p.w);

        const int base = idx * 4;
        if (t.x > best_v) { best_v = t.x; best_i = base + 0; }
        if (t.y > best_v) { best_v = t.y; best_i = base + 1; }
        if (t.z > best_v) { best_v = t.z; best_i = base + 2; }
        if (t.w > best_v) { best_v = t.w; best_i = base + 3; }
    }

    // Warp reduction: sum + (max value, min index on tie).
    #pragma unroll
    for (int off = 16; off > 0; off >>= 1) {
        float ov = __shfl_down_sync(FULLMASK, best_v, off);
        int   oi = __shfl_down_sync(FULLMASK, best_i, off);
        float os = __shfl_down_sync(FULLMASK, sumexp, off);
        sumexp += os;
        if (ov > best_v || (ov == best_v && oi < best_i)) { best_v = ov; best_i = oi; }
    }

    if (lane == 0) { sh_v[warp] = best_v; sh_i[warp] = best_i; sh_s[warp] = sumexp; }
    __syncthreads();

    // ---- Parallel epilogue: warp 0 only (R7 structure) ----
    if (warp == 0) {
        float v = (lane < NWARPS) ? sh_v[lane] : -3.402823466e38f;
        int   i = (lane < NWARPS) ? sh_i[lane] : 0x7fffffff;
        float s = (lane < NWARPS) ? sh_s[lane] : 0.0f;
        #pragma unroll
        for (int off = NWARPS / 2; off > 0; off >>= 1) {
            float ov = __shfl_down_sync(FULLMASK, v, off);
            int   oi = __shfl_down_sync(FULLMASK, i, off);
            float os = __shfl_down_sync(FULLMASK, s, off);
            s += os;
            if (ov > v || (ov == v && oi < i)) { v = ov; i = oi; }
        }
        const float S     = __shfl_sync(FULLMASK, s, 0);
        const int   label = __shfl_sync(FULLMASK, i, 0);
        const float invS  = 1.0f / S;

        const int len = tree_lens[label];

        // Parallel path gather: lane k handles level k (pr=0 beyond len).
        float pr = 0.0f;
        if (lane < len && lane < D) {
            const int node = tree_paths[(size_t)label * D + lane];
            pr = expf(y_pred[(size_t)b * NCLS + node]) * invS;
        }

        // Reverse inclusive suffix scan: sarr[k] = sum_{j>=k} pr[j].
        float sarr = pr;
        #pragma unroll
        for (int off = 1; off < 32; off <<= 1) {
            float t = __shfl_down_sync(FULLMASK, sarr, off);
            if (lane + off < 32) sarr += t;
        }
        float snext = __shfl_down_sync(FULLMASK, sarr, 1);
        if (lane == 31) snext = 0.0f;

        // Per-level loss terms (valid: k < len-1).
        float term = 0.0f;
        if (lane < len - 1) {
            const float cond = sarr / (snext + EPSF);
            const float h    = (float)(len - 1 - lane);
            term = expf(-DEPTH_PARAM * h) * logf(cond + EPSF);
        }
        #pragma unroll
        for (int off = 16; off > 0; off >>= 1)
            term += __shfl_down_sync(FULLMASK, term, off);

        if (lane == 0) {
            atomicAdd(&g_acc, (double)(-class_w[label] * term));

            // Last-row-done finalize: make our add visible, then count in.
            __threadfence();
            const unsigned ticket = atomicAdd(&g_done, 1u);
            if (ticket == NBATCH - 1) {
                const unsigned long long raw =
                    atomicExch(reinterpret_cast<unsigned long long*>(&g_acc), 0ull);
                const double acc = __longlong_as_double((long long)raw);
                out[0] = (float)(acc / (double)NBATCH);
                g_done = 0;   // reset for the next launch (stream-ordered)
            }
        }
    }
}

extern "C" void kernel_launch(void* const* d_in, const int* in_sizes, int n_in,
                              void* d_out, int out_size)
{
    const float* y_pred     = (const float*)d_in[0];
    const float* y_true     = (const float*)d_in[1];
    const float* class_w    = (const float*)d_in[2];
    const int*   tree_paths = (const int*)  d_in[3];
    const int*   tree_lens  = (const int*)  d_in[4];

    const int D = in_sizes[3] / NCLS;

    chce_fused_kernel<<<NBATCH, THREADS>>>(y_pred, y_true, class_w,
                                           tree_paths, tree_lens,
                                           (float*)d_out, D);
}

// round 12
// speedup vs baseline: 1.0478x; 1.0478x over previous
#include <cuda_runtime.h>

#define NCLS   8192
#define NBATCH 8192
#define THREADS 256
#define NWARPS (THREADS / 32)
#define QUARTER (NCLS / 4)          // 2048 elems per stream-quarter
#define NIT_W  (QUARTER / (32 * 4)) // 16 float4-iters per warp
#define EPSF 1e-8f
#define DEPTH_PARAM 0.1f
#define FULLMASK 0xffffffffu

// Global accumulator + completion counter. Zero-initialized at module load;
// the last-finishing row resets both before the kernel ends, so every
// kernel_launch call starts from identical state.
__device__ double       g_acc;
__device__ unsigned int g_done;

__global__ __launch_bounds__(THREADS)
void chce_fused_kernel(const float* __restrict__ y_pred,
                       const float* __restrict__ y_true,
                       const float* __restrict__ class_w,
                       const int*   __restrict__ tree_paths,
                       const int*   __restrict__ tree_lens,
                       float*       __restrict__ out,
                       int D)
{
    const int b    = blockIdx.x;
    const int tid  = threadIdx.x;
    const int lane = tid & 31;
    const int warp = tid >> 5;

    __shared__ float sh_s[4];   // sum-exp partials (warps 0-3)
    __shared__ float sh_v[4];   // argmax partials  (warps 4-7)
    __shared__ int   sh_i[4];

    // Warp stream-specialization: warps 0-3 stream contiguous quarters of
    // y_pred; warps 4-7 stream contiguous quarters of y_true. Each warp's
    // requests stay within one array region -> same-page DRAM bursts.
    const int q = warp & 3;                       // quarter index

    if (warp < 4) {
        const float4* yp = reinterpret_cast<const float4*>(y_pred)
                         + (size_t)b * (NCLS / 4) + q * (QUARTER / 4);
        float sumexp = 0.0f;
        #pragma unroll
        for (int it = 0; it < NIT_W; ++it) {
            float4 p = __ldcs(&yp[it * 32 + lane]);
            sumexp += __expf(p.x) + __expf(p.y) + __expf(p.z) + __expf(p.w);
        }
        #pragma unroll
        for (int off = 16; off > 0; off >>= 1)
            sumexp += __shfl_down_sync(FULLMASK, sumexp, off);
        if (lane == 0) sh_s[q] = sumexp;
    } else {
        const float4* yt = reinterpret_cast<const float4*>(y_true)
                         + (size_t)b * (NCLS / 4) + q * (QUARTER / 4);
        const int ebase = q * QUARTER;            // element offset of quarter
        float best_v = -3.402823466e38f;
        int   best_i = 0;
        #pragma unroll
        for (int it = 0; it < NIT_W; ++it) {
            float4 t = __ldcs(&yt[it * 32 + lane]);
            const int base = ebase + (it * 32 + lane) * 4;
            if (t.x > best_v) { best_v = t.x; best_i = base + 0; }
            if (t.y > best_v) { best_v = t.y; best_i = base + 1; }
            if (t.z > best_v) { best_v = t.z; best_i = base + 2; }
            if (t.w > best_v) { best_v = t.w; best_i = base + 3; }
        }
        #pragma unroll
        for (int off = 16; off > 0; off >>= 1) {
            float ov = __shfl_down_sync(FULLMASK, best_v, off);
            int   oi = __shfl_down_sync(FULLMASK, best_i, off);
            if (ov > best_v || (ov == best_v && oi < best_i)) { best_v = ov; best_i = oi; }
        }
        if (lane == 0) { sh_v[q] = best_v; sh_i[q] = best_i; }
    }
    __syncthreads();

    // ---- Parallel epilogue: warp 0 only ----
    if (warp == 0) {
        // Combine 4 sum partials and 4 argmax partials in registers.
        float s = (lane < 4) ? sh_s[lane] : 0.0f;
        float v = (lane < 4) ? sh_v[lane] : -3.402823466e38f;
        int   i = (lane < 4) ? sh_i[lane] : 0x7fffffff;
        #pragma unroll
        for (int off = 2; off > 0; off >>= 1) {
            float os = __shfl_down_sync(FULLMASK, s, off);
            float ov = __shfl_down_sync(FULLMASK, v, off);
            int   oi = __shfl_down_sync(FULLMASK, i, off);
            s += os;
            if (ov > v || (ov == v && oi < i)) { v = ov; i = oi; }
        }
        const float S     = __shfl_sync(FULLMASK, s, 0);
        const int   label = __shfl_sync(FULLMASK, i, 0);
        const float invS  = 1.0f / S;

        const int len = tree_lens[label];

        // Parallel path gather: lane k handles level k (pr=0 beyond len).
        float pr = 0.0f;
        if (lane < len && lane < D) {
            const int node = tree_paths[(size_t)label * D + lane];
            pr = expf(y_pred[(size_t)b * NCLS + node]) * invS;
        }

        // Reverse inclusive suffix scan: sarr[k] = sum_{j>=k} pr[j].
        float sarr = pr;
        #pragma unroll
        for (int off = 1; off < 32; off <<= 1) {
            float t = __shfl_down_sync(FULLMASK, sarr, off);
            if (lane + off < 32) sarr += t;
        }
        float snext = __shfl_down_sync(FULLMASK, sarr, 1);
        if (lane == 31) snext = 0.0f;

        // Per-level loss terms (valid: k < len-1).
        float term = 0.0f;
        if (lane < len - 1) {
            const float cond = sarr / (snext + EPSF);
            const float h    = (float)(len - 1 - lane);
            term = expf(-DEPTH_PARAM * h) * logf(cond + EPSF);
        }
        #pragma unroll
        for (int off = 16; off > 0; off >>= 1)
            term += __shfl_down_sync(FULLMASK, term, off);

        if (lane == 0) {
            atomicAdd(&g_acc, (double)(-class_w[label] * term));

            // Last-row-done finalize: make our add visible, then count in.
            __threadfence();
            const unsigned ticket = atomicAdd(&g_done, 1u);
            if (ticket == NBATCH - 1) {
                const unsigned long long raw =
                    atomicExch(reinterpret_cast<unsigned long long*>(&g_acc), 0ull);
                const double acc = __longlong_as_double((long long)raw);
                out[0] = (float)(acc / (double)NBATCH);
                g_done = 0;   // reset for the next launch (stream-ordered)
            }
        }
    }
}

extern "C" void kernel_launch(void* const* d_in, const int* in_sizes, int n_in,
                              void* d_out, int out_size)
{
    const float* y_pred     = (const float*)d_in[0];
    const float* y_true     = (const float*)d_in[1];
    const float* class_w    = (const float*)d_in[2];
    const int*   tree_paths = (const int*)  d_in[3];
    const int*   tree_lens  = (const int*)  d_in[4];

    const int D = in_sizes[3] / NCLS;

    chce_fused_kernel<<<NBATCH, THREADS>>>(y_pred, y_true, class_w,
                                           tree_paths, tree_lens,
                                           (float*)d_out, D);
}